// round 10
// baseline (speedup 1.0000x reference)
#include <cuda_runtime.h>
#include <cstdint>
#include <cstddef>
#include <math.h>

#define BATCH 16384
#define DIM   1024
#define NNODES (2*BATCH)

// ---------------- scratch (static device memory: allowed) ----------------
__device__ float g_ra  [(size_t)BATCH * DIM];          // tf32-rounded audio
__device__ float g_rt  [(size_t)BATCH * DIM];          // tf32-rounded text
__device__ float g_rWa [(size_t)DIM * DIM];
__device__ float g_rWt [(size_t)DIM * DIM];
__device__ float g_rW1 [(size_t)2 * DIM * DIM];
__device__ float g_rW2 [(size_t)DIM * 2 * DIM];
__device__ float g_rWf [(size_t)DIM * DIM];
__device__ float g_pre  [(size_t)NNODES * DIM];        // proj out pre-LN (interleaved)
__device__ float g_nodes[(size_t)NNODES * DIM];        // post LN+relu (rounded)
__device__ float g_x1   [(size_t)NNODES * 2 * DIM];    // gat1 out (rounded)
__device__ float g_x2   [(size_t)NNODES * DIM];        // gat2 out
__device__ float g_xm   [(size_t)BATCH * DIM];         // pair-mean (rounded)
__device__ float g_fcb  [(size_t)BATCH * DIM];         // fc out pre-LN

__device__ __forceinline__ float tf32r(float x) {
    uint32_t y;
    asm("cvt.rna.tf32.f32 %0, %1;" : "=r"(y) : "f"(x));
    return __uint_as_float(y);
}

__device__ __forceinline__ void cp_async16(uint32_t smem_dst, const void* gsrc) {
    asm volatile("cp.async.cg.shared.global [%0], [%1], 16;\n"
                 :: "r"(smem_dst), "l"(gsrc));
}

// ---------------- tf32 GEMM: C = A @ W^T (+bias, opt relu, opt round) ----------------
// Block tile 128(M) x 128(N) x 32(K); 8 warps of 32x64; 3-stage cp.async ring;
// 2 CTAs per SM (108KB smem/CTA). Operands pre-rounded to tf32 (NO cvt in loop).
// K within each k8 permuted (pos j <-> k=2j / 2j-7): float2 LDS, lo.x->pos tg,
// lo.y->pos tg+4. K-sum order-invariant.
#define BM2 128
#define BN2 128
#define BK2 32
#define NTHR 256
#define RSTRIDE 36                        // floats per smem row (144B, 16B aligned)
#define A_STG (BM2 * RSTRIDE)             // 4608 floats
#define B_STG (BN2 * RSTRIDE)             // 4608 floats
#define STG_FLOATS (A_STG + B_STG)        // 9216 floats = 36864 B
#define NSTAGE 3
#define SMEM_BYTES (NSTAGE * STG_FLOATS * 4)   // 110592 B

template<int RELU, int ROUND>
__launch_bounds__(NTHR, 2)
__global__ void gemm_big(const float* __restrict__ A, const float* __restrict__ W,
                         const float* __restrict__ bias, float* __restrict__ C,
                         int K, int ldc, int rowmul, int rowadd)
{
    extern __shared__ float smem[];

    const int tid  = threadIdx.x;
    const int warp = tid >> 5;           // 0..7
    const int lane = tid & 31;
    const int g    = lane >> 2;          // 0..7
    const int tg   = lane & 3;           // 0..3
    const int wm   = (warp & 3) * 32;    // 0/32/64/96
    const int wn   = (warp >> 2) * 64;   // 0/64
    const int mblk = blockIdx.y * BM2;
    const int nblk = blockIdx.x * BN2;

    uint32_t smem_base;
    {
        void* p = smem;
        smem_base = (uint32_t)__cvta_generic_to_shared(p);
    }

    float acc[2][8][4];
#pragma unroll
    for (int i = 0; i < 2; i++)
#pragma unroll
        for (int j = 0; j < 8; j++)
#pragma unroll
            for (int q = 0; q < 4; q++) acc[i][j][q] = 0.f;

    // issue cp.async for one K-stage (A:128rows x 8chunks + B same = 2048 chunks)
    auto issue = [&](int st, int kb) {
        const int k0 = kb * BK2;
        const uint32_t stg = smem_base + (uint32_t)(st * STG_FLOATS) * 4u;
#pragma unroll
        for (int i = 0; i < 4; i++) {
            const int c  = tid + i * NTHR;      // 0..1023
            const int m  = c >> 3;              // 0..127
            const int kc = (c & 7) * 4;         // 0..28
            cp_async16(stg + (uint32_t)(m * RSTRIDE + kc) * 4u,
                       A + (size_t)(mblk + m) * K + k0 + kc);
            cp_async16(stg + (uint32_t)(A_STG + m * RSTRIDE + kc) * 4u,
                       W + (size_t)(nblk + m) * K + k0 + kc);
        }
    };

    auto compute = [&](int st) {
        const float* Ast = smem + st * STG_FLOATS;
        const float* Bst = Ast + A_STG;
#pragma unroll
        for (int k8 = 0; k8 < 4; k8++) {
            const int kb8 = k8 * 8;
            uint32_t af[2][4];
#pragma unroll
            for (int i = 0; i < 2; i++) {
                const int m0 = wm + i * 16;
                const float2 lo = *(const float2*)(Ast + (m0 + g    ) * RSTRIDE + kb8 + 2 * tg);
                const float2 hi = *(const float2*)(Ast + (m0 + g + 8) * RSTRIDE + kb8 + 2 * tg);
                af[i][0] = __float_as_uint(lo.x);
                af[i][1] = __float_as_uint(hi.x);
                af[i][2] = __float_as_uint(lo.y);
                af[i][3] = __float_as_uint(hi.y);
            }
            uint32_t bfr[8][2];
#pragma unroll
            for (int j = 0; j < 8; j++) {
                const int n0 = wn + j * 8;
                const float2 b2v = *(const float2*)(Bst + (n0 + g) * RSTRIDE + kb8 + 2 * tg);
                bfr[j][0] = __float_as_uint(b2v.x);
                bfr[j][1] = __float_as_uint(b2v.y);
            }
#pragma unroll
            for (int i = 0; i < 2; i++)
#pragma unroll
                for (int j = 0; j < 8; j++)
                    asm volatile(
                        "mma.sync.aligned.m16n8k8.row.col.f32.tf32.tf32.f32 "
                        "{%0,%1,%2,%3}, {%4,%5,%6,%7}, {%8,%9}, {%0,%1,%2,%3};\n"
                        : "+f"(acc[i][j][0]), "+f"(acc[i][j][1]),
                          "+f"(acc[i][j][2]), "+f"(acc[i][j][3])
                        : "r"(af[i][0]), "r"(af[i][1]), "r"(af[i][2]), "r"(af[i][3]),
                          "r"(bfr[j][0]), "r"(bfr[j][1]));
        }
    };

    const int KT = K / BK2;

    // prefetch NSTAGE-1 stages
#pragma unroll
    for (int p = 0; p < NSTAGE - 1; p++) {
        if (p < KT) issue(p, p);
        asm volatile("cp.async.commit_group;\n" ::);
    }

    for (int kb = 0; kb < KT; kb++) {
        asm volatile("cp.async.wait_group %0;\n" :: "n"(NSTAGE - 2));
        __syncthreads();
        if (kb + NSTAGE - 1 < KT) issue((kb + NSTAGE - 1) % NSTAGE, kb + NSTAGE - 1);
        asm volatile("cp.async.commit_group;\n" ::);
        compute(kb % NSTAGE);
        __syncthreads();
    }

    // epilogue: bias (+relu, +round), float2 stores
#pragma unroll
    for (int i = 0; i < 2; i++) {
        const int row_a = mblk + wm + i * 16 + g;
        const int row_b = row_a + 8;
#pragma unroll
        for (int j = 0; j < 8; j++) {
            const int col = nblk + wn + j * 8 + 2 * tg;
            const float2 bv = *(const float2*)(bias + col);
            float o0 = acc[i][j][0] + bv.x;
            float o1 = acc[i][j][1] + bv.y;
            float o2 = acc[i][j][2] + bv.x;
            float o3 = acc[i][j][3] + bv.y;
            if (RELU) {
                o0 = fmaxf(o0, 0.f); o1 = fmaxf(o1, 0.f);
                o2 = fmaxf(o2, 0.f); o3 = fmaxf(o3, 0.f);
            }
            if (ROUND) {
                o0 = tf32r(o0); o1 = tf32r(o1);
                o2 = tf32r(o2); o3 = tf32r(o3);
            }
            const size_t ca = (size_t)(rowmul * row_a + rowadd) * ldc + col;
            const size_t cb = (size_t)(rowmul * row_b + rowadd) * ldc + col;
            *(float2*)(C + ca) = make_float2(o0, o1);
            *(float2*)(C + cb) = make_float2(o2, o3);
        }
    }
}

// ---------------- tf32-RNA rounding copy ----------------
__global__ void round_kernel(const float* __restrict__ in, float* __restrict__ out,
                             size_t n4)
{
    const size_t stride = (size_t)gridDim.x * blockDim.x;
    for (size_t i = (size_t)blockIdx.x * blockDim.x + threadIdx.x; i < n4; i += stride) {
        float4 v = ((const float4*)in)[i];
        v.x = tf32r(v.x); v.y = tf32r(v.y); v.z = tf32r(v.z); v.w = tf32r(v.w);
        ((float4*)out)[i] = v;
    }
}

// ---------------- pair-mean (rounded): xm[r] = tf32(0.5*(x2[2r]+x2[2r+1])) ----------
__global__ void mean_kernel(const float* __restrict__ x2, float* __restrict__ xm)
{
    const size_t f4 = (size_t)blockIdx.x * 256 + threadIdx.x;
    const size_t row  = f4 >> 8;
    const size_t col4 = f4 & 255;
    const float4 u = ((const float4*)(x2 + (2*row)     * DIM))[col4];
    const float4 v = ((const float4*)(x2 + (2*row + 1) * DIM))[col4];
    ((float4*)(xm + row * DIM))[col4] =
        make_float4(tf32r(0.5f*(u.x+v.x)), tf32r(0.5f*(u.y+v.y)),
                    tf32r(0.5f*(u.z+v.z)), tf32r(0.5f*(u.w+v.w)));
}

// ---------------- LayerNorm (+opt relu, opt round), row length DIM ----------------
__global__ void ln_kernel(const float* __restrict__ in, float* __restrict__ out,
                          const float* __restrict__ g_e, const float* __restrict__ b_e,
                          const float* __restrict__ g_o, const float* __restrict__ b_o,
                          int relu, int rnd)
{
    const int row = blockIdx.x;
    const int tid = threadIdx.x;
    const float* gg = (row & 1) ? g_o : g_e;
    const float* bb = (row & 1) ? b_o : b_e;

    float4 v = ((const float4*)(in + (size_t)row * DIM))[tid];
    float s = v.x + v.y + v.z + v.w;
    float q = v.x*v.x + v.y*v.y + v.z*v.z + v.w*v.w;
#pragma unroll
    for (int off = 16; off; off >>= 1) {
        s += __shfl_xor_sync(0xffffffffu, s, off);
        q += __shfl_xor_sync(0xffffffffu, q, off);
    }
    __shared__ float ss[8], sq[8];
    __shared__ float mu_s, rs_s;
    if ((tid & 31) == 0) { ss[tid >> 5] = s; sq[tid >> 5] = q; }
    __syncthreads();
    if (tid == 0) {
        float S = 0.f, Q = 0.f;
#pragma unroll
        for (int i = 0; i < 8; i++) { S += ss[i]; Q += sq[i]; }
        const float mu = S * (1.0f / DIM);
        const float var = Q * (1.0f / DIM) - mu * mu;
        mu_s = mu;
        rs_s = rsqrtf(var + 1e-5f);
    }
    __syncthreads();
    const float mu = mu_s, rs = rs_s;
    const float4 gv = ((const float4*)gg)[tid];
    const float4 bv = ((const float4*)bb)[tid];
    v.x = (v.x - mu) * rs * gv.x + bv.x;
    v.y = (v.y - mu) * rs * gv.y + bv.y;
    v.z = (v.z - mu) * rs * gv.z + bv.z;
    v.w = (v.w - mu) * rs * gv.w + bv.w;
    if (relu) {
        v.x = fmaxf(v.x, 0.f); v.y = fmaxf(v.y, 0.f);
        v.z = fmaxf(v.z, 0.f); v.w = fmaxf(v.w, 0.f);
    }
    if (rnd) { v.x = tf32r(v.x); v.y = tf32r(v.y); v.z = tf32r(v.z); v.w = tf32r(v.w); }
    ((float4*)(out + (size_t)row * DIM))[tid] = v;
}

__device__ __forceinline__ float lrelu(float v) { return v > 0.f ? v : 0.2f * v; }

// ---------------- GAT1 fixup rows 0,1 (H=2, in=1024, out/head=1024) ----------------
__global__ void fixup_gat1(const float* __restrict__ nodes, const float* __restrict__ W1,
                           const float* __restrict__ as1, const float* __restrict__ ad1,
                           const float* __restrict__ b1, float* __restrict__ x1)
{
    __shared__ float sh_n[2][DIM];
    __shared__ float sh_xp[2][2 * DIM];
    __shared__ float sh_sd[8];
    __shared__ float sh_w[8];
    const int tid = threadIdx.x, warp = tid >> 5, lane = tid & 31;

    for (int i = tid; i < 2 * DIM; i += 256) sh_n[i >> 10][i & 1023] = nodes[i];
    __syncthreads();

    for (int o = warp; o < 4096; o += 8) {
        const int n = o >> 11, oc = o & 2047;
        const float* wr = W1 + (size_t)oc * DIM;
        float p = 0.f;
        for (int k = lane; k < DIM; k += 32) p += sh_n[n][k] * wr[k];
#pragma unroll
        for (int off = 16; off; off >>= 1) p += __shfl_xor_sync(0xffffffffu, p, off);
        if (lane == 0) sh_xp[n][oc] = p;
    }
    __syncthreads();

    if (warp < 8) {
        const int n = warp >> 2, h = (warp >> 1) & 1, isd = warp & 1;
        const float* av = (isd ? ad1 : as1) + h * DIM;
        float p = 0.f;
        for (int k = lane; k < DIM; k += 32) p += sh_xp[n][h * DIM + k] * av[k];
#pragma unroll
        for (int off = 16; off; off >>= 1) p += __shfl_xor_sync(0xffffffffu, p, off);
        if (lane == 0) sh_sd[n * 4 + h * 2 + isd] = p;
    }
    __syncthreads();

    if (tid == 0) {
#pragma unroll
        for (int h = 0; h < 2; h++) {
            const float s0 = sh_sd[0*4 + h*2 + 0], d0 = sh_sd[0*4 + h*2 + 1];
            const float s1 = sh_sd[1*4 + h*2 + 0], d1 = sh_sd[1*4 + h*2 + 1];
            const float e00 = lrelu(s0 + d0), e10 = lrelu(s1 + d0);
            const float e11 = lrelu(s1 + d1), e01 = lrelu(s0 + d1);
            const float m0 = fmaxf(e00, e10);
            const float w00 = expf(e00 - m0), w10 = expf(e10 - m0);
            const float inv0 = 1.f / (w00 + w10);
            const float m1 = fmaxf(e11, e01);
            const float w11 = expf(e11 - m1), w01 = expf(e01 - m1);
            const float inv1 = 1.f / (w11 + w01);
            sh_w[h*4+0] = w00 * inv0;
            sh_w[h*4+1] = w10 * inv0;
            sh_w[h*4+2] = w11 * inv1;
            sh_w[h*4+3] = w01 * inv1;
        }
    }
    __syncthreads();

    for (int idx = tid; idx < 2 * DIM; idx += 256) {
        const int h = idx >> 10;
        const float o0 = sh_w[h*4+0] * sh_xp[0][idx] + sh_w[h*4+1] * sh_xp[1][idx];
        const float o1 = sh_w[h*4+2] * sh_xp[1][idx] + sh_w[h*4+3] * sh_xp[0][idx];
        x1[idx]           = tf32r(fmaxf(o0 + b1[idx], 0.f));
        x1[2 * DIM + idx] = tf32r(fmaxf(o1 + b1[idx], 0.f));
    }
}

// ---------------- GAT2 fixup rows 0,1 (H=1, in=2048, out=1024) ----------------
__global__ void fixup_gat2(const float* __restrict__ x1, const float* __restrict__ W2,
                           const float* __restrict__ as2, const float* __restrict__ ad2,
                           const float* __restrict__ b2, float* __restrict__ x2)
{
    __shared__ float sh_in[2][2 * DIM];
    __shared__ float sh_xp[2][DIM];
    __shared__ float sh_sd[4];
    __shared__ float sh_w[4];
    const int tid = threadIdx.x, warp = tid >> 5, lane = tid & 31;

    for (int i = tid; i < 4 * DIM; i += 256) sh_in[i >> 11][i & 2047] = x1[i];
    __syncthreads();

    for (int o = warp; o < 2048; o += 8) {
        const int n = o >> 10, oc = o & 1023;
        const float* wr = W2 + (size_t)oc * (2 * DIM);
        float p = 0.f;
        for (int k = lane; k < 2 * DIM; k += 32) p += sh_in[n][k] * wr[k];
#pragma unroll
        for (int off = 16; off; off >>= 1) p += __shfl_xor_sync(0xffffffffu, p, off);
        if (lane == 0) sh_xp[n][oc] = p;
    }
    __syncthreads();

    if (warp < 4) {
        const int n = warp >> 1, isd = warp & 1;
        const float* av = isd ? ad2 : as2;
        float p = 0.f;
        for (int k = lane; k < DIM; k += 32) p += sh_xp[n][k] * av[k];
#pragma unroll
        for (int off = 16; off; off >>= 1) p += __shfl_xor_sync(0xffffffffu, p, off);
        if (lane == 0) sh_sd[n * 2 + isd] = p;
    }
    __syncthreads();

    if (tid == 0) {
        const float s0 = sh_sd[0], d0 = sh_sd[1], s1 = sh_sd[2], d1 = sh_sd[3];
        const float e00 = lrelu(s0 + d0), e10 = lrelu(s1 + d0);
        const float e11 = lrelu(s1 + d1), e01 = lrelu(s0 + d1);
        const float m0 = fmaxf(e00, e10);
        const float w00 = expf(e00 - m0), w10 = expf(e10 - m0);
        const float inv0 = 1.f / (w00 + w10);
        const float m1 = fmaxf(e11, e01);
        const float w11 = expf(e11 - m1), w01 = expf(e01 - m1);
        const float inv1 = 1.f / (w11 + w01);
        sh_w[0] = w00 * inv0; sh_w[1] = w10 * inv0;
        sh_w[2] = w11 * inv1; sh_w[3] = w01 * inv1;
    }
    __syncthreads();

    for (int idx = tid; idx < DIM; idx += 256) {
        const float o0 = sh_w[0] * sh_xp[0][idx] + sh_w[1] * sh_xp[1][idx];
        const float o1 = sh_w[2] * sh_xp[1][idx] + sh_w[3] * sh_xp[0][idx];
        x2[idx]       = o0 + b2[idx];
        x2[DIM + idx] = o1 + b2[idx];
    }
}

// ---------------- launch ----------------
extern "C" void kernel_launch(void* const* d_in, const int* in_sizes, int n_in,
                              void* d_out, int out_size)
{
    const float* audio = (const float*)d_in[0];
    const float* text  = (const float*)d_in[1];
    const float* Wa    = (const float*)d_in[2];
    const float* ba    = (const float*)d_in[3];
    const float* lna_g = (const float*)d_in[4];
    const float* lna_b = (const float*)d_in[5];
    const float* Wt    = (const float*)d_in[6];
    const float* bt    = (const float*)d_in[7];
    const float* lnt_g = (const float*)d_in[8];
    const float* lnt_b = (const float*)d_in[9];
    const float* W1    = (const float*)d_in[10];
    const float* as1   = (const float*)d_in[11];
    const float* ad1   = (const float*)d_in[12];
    const float* b1    = (const float*)d_in[13];
    const float* W2    = (const float*)d_in[14];
    const float* as2   = (const float*)d_in[15];
    const float* ad2   = (const float*)d_in[16];
    const float* b2    = (const float*)d_in[17];
    const float* Wf    = (const float*)d_in[18];
    const float* bf    = (const float*)d_in[19];
    const float* lnf_g = (const float*)d_in[20];
    const float* lnf_b = (const float*)d_in[21];

    float *ra, *rt, *rWa, *rWt, *rW1, *rW2, *rWf;
    float *pre, *nodes, *x1, *x2, *xm, *fcb;
    cudaGetSymbolAddress((void**)&ra,  g_ra);
    cudaGetSymbolAddress((void**)&rt,  g_rt);
    cudaGetSymbolAddress((void**)&rWa, g_rWa);
    cudaGetSymbolAddress((void**)&rWt, g_rWt);
    cudaGetSymbolAddress((void**)&rW1, g_rW1);
    cudaGetSymbolAddress((void**)&rW2, g_rW2);
    cudaGetSymbolAddress((void**)&rWf, g_rWf);
    cudaGetSymbolAddress((void**)&pre,   g_pre);
    cudaGetSymbolAddress((void**)&nodes, g_nodes);
    cudaGetSymbolAddress((void**)&x1,    g_x1);
    cudaGetSymbolAddress((void**)&x2,    g_x2);
    cudaGetSymbolAddress((void**)&xm,    g_xm);
    cudaGetSymbolAddress((void**)&fcb,   g_fcb);

    cudaFuncSetAttribute(gemm_big<0,0>, cudaFuncAttributeMaxDynamicSharedMemorySize, SMEM_BYTES);
    cudaFuncSetAttribute(gemm_big<1,1>, cudaFuncAttributeMaxDynamicSharedMemorySize, SMEM_BYTES);

    const size_t nBD4 = (size_t)BATCH * DIM / 4;
    const size_t nDD4 = (size_t)DIM * DIM / 4;

    // pre-round all GEMM operands to tf32-RNA bit patterns (big grids)
    round_kernel<<<8192, 256>>>(audio, ra, nBD4);
    round_kernel<<<8192, 256>>>(text,  rt, nBD4);
    round_kernel<<<4096, 256>>>(Wa, rWa, nDD4);
    round_kernel<<<4096, 256>>>(Wt, rWt, nDD4);
    round_kernel<<<8192, 256>>>(W1, rW1, 2 * nDD4);
    round_kernel<<<8192, 256>>>(W2, rW2, 2 * nDD4);
    round_kernel<<<4096, 256>>>(Wf, rWf, nDD4);

    dim3 blk(NTHR);

    // proj_audio / proj_text -> interleaved pre-LN rows (row = 2*m + {0,1})
    gemm_big<0,0><<<dim3(8, 128), blk, SMEM_BYTES>>>(ra, rWa, ba, pre, 1024, 1024, 2, 0);
    gemm_big<0,0><<<dim3(8, 128), blk, SMEM_BYTES>>>(rt, rWt, bt, pre, 1024, 1024, 2, 1);
    // LN + relu + round (nodes feeds gat1 as operand)
    ln_kernel<<<NNODES, 256>>>(pre, nodes, lna_g, lna_b, lnt_g, lnt_b, 1, 1);
    // gat1 self-loop path: relu(xp + b1), rounded (x1 feeds gat2 as operand)
    gemm_big<1,1><<<dim3(16, 256), blk, SMEM_BYTES>>>(nodes, rW1, b1, x1, 1024, 2048, 1, 0);
    fixup_gat1<<<1, 256>>>(nodes, W1, as1, ad1, b1, x1);
    // gat2 self-loop path: xp + b2 (x2 feeds mean, which rounds)
    gemm_big<0,0><<<dim3(8, 256), blk, SMEM_BYTES>>>(x1, rW2, b2, x2, 2048, 1024, 1, 0);
    fixup_gat2<<<1, 256>>>(x1, W2, as2, ad2, b2, x2);
    // pair-mean (rounded) then fc
    mean_kernel<<<BATCH, 256>>>(x2, xm);
    gemm_big<0,0><<<dim3(8, 128), blk, SMEM_BYTES>>>(xm, rWf, bf, fcb, 1024, 1024, 1, 0);
    // final LN -> out
    ln_kernel<<<BATCH, 256>>>(fcb, (float*)d_out, lnf_g, lnf_b, lnf_g, lnf_b, 0, 0);
}

// round 11
// speedup vs baseline: 1.1107x; 1.1107x over previous
#include <cuda_runtime.h>
#include <cstdint>
#include <cstddef>
#include <math.h>

#define BATCH 16384
#define DIM   1024
#define NNODES (2*BATCH)

// ---------------- scratch (static device memory: allowed) ----------------
__device__ float g_pre  [(size_t)NNODES * DIM];        // proj out pre-LN (interleaved)
__device__ float g_nodes[(size_t)NNODES * DIM];        // post LN+relu
__device__ float g_x1   [(size_t)NNODES * 2 * DIM];    // gat1 out (post bias+relu)
__device__ float g_xm   [(size_t)BATCH * DIM];         // pair-mean of gat2 out (fused)
__device__ float g_fcb  [(size_t)BATCH * DIM];         // fc out pre-LN

__device__ __forceinline__ uint32_t tf32bits(float x) {
    uint32_t y;
    asm("cvt.rna.tf32.f32 %0, %1;" : "=r"(y) : "f"(x));
    return y;
}

__device__ __forceinline__ void cp_async16(uint32_t smem_dst, const void* gsrc) {
    asm volatile("cp.async.cg.shared.global [%0], [%1], 16;\n"
                 :: "r"(smem_dst), "l"(gsrc));
}

// ---------------- tf32 GEMM: C = A @ W^T (+bias, opt relu, opt fused pair-mean) ----
// Block tile 128(M) x 128(N) x 16(K); 8 warps of 32x64; 4-stage cp.async ring;
// 2 CTAs per SM (98KB smem/CTA, <=128 regs). ONE barrier per mainloop iteration.
// cvt.rna.tf32 post-LDS. K within each k8 permuted (pos j <-> k=2j / 2j-7):
// float2 LDS, lo.x->pos tg, lo.y->pos tg+4 (K-sum order-invariant).
// MEAN=1: C row r receives 0.5*(out[2r]+out[2r+1]) via shfl across adjacent g lanes.
#define BM2 128
#define BN2 128
#define BK2 16
#define NTHR 256
#define RSTRIDE 24                        // floats per smem row (96B, 16B aligned)
#define A_STG (BM2 * RSTRIDE)             // 3072 floats
#define B_STG (BM2 * RSTRIDE)             // 3072 floats
#define STG_FLOATS (A_STG + B_STG)        // 6144 floats = 24576 B
#define NSTAGE 4
#define SMEM_BYTES (NSTAGE * STG_FLOATS * 4)   // 98304 B

template<int RELU, int MEAN>
__launch_bounds__(NTHR, 2)
__global__ void gemm_big(const float* __restrict__ A, const float* __restrict__ W,
                         const float* __restrict__ bias, float* __restrict__ C,
                         int K, int ldc, int rowmul, int rowadd)
{
    extern __shared__ float smem[];

    const int tid  = threadIdx.x;
    const int warp = tid >> 5;           // 0..7
    const int lane = tid & 31;
    const int g    = lane >> 2;          // 0..7
    const int tg   = lane & 3;           // 0..3
    const int wm   = (warp & 3) * 32;    // 0/32/64/96
    const int wn   = (warp >> 2) * 64;   // 0/64
    const int mblk = blockIdx.y * BM2;
    const int nblk = blockIdx.x * BN2;

    uint32_t smem_base;
    {
        void* p = smem;
        smem_base = (uint32_t)__cvta_generic_to_shared(p);
    }

    float acc[2][8][4];
#pragma unroll
    for (int i = 0; i < 2; i++)
#pragma unroll
        for (int j = 0; j < 8; j++)
#pragma unroll
            for (int q = 0; q < 4; q++) acc[i][j][q] = 0.f;

    // issue cp.async for one K-stage (1024 16B-chunks, 4 per thread)
    auto issue = [&](int st, int kb) {
        const int k0 = kb * BK2;
        const uint32_t stg = smem_base + (uint32_t)(st * STG_FLOATS) * 4u;
#pragma unroll
        for (int i = 0; i < 2; i++) {
            const int c  = tid + i * NTHR;      // 0..511
            const int m  = c >> 2;              // 0..127
            const int kc = (c & 3) * 4;
            cp_async16(stg + (uint32_t)(m * RSTRIDE + kc) * 4u,
                       A + (size_t)(mblk + m) * K + k0 + kc);
            cp_async16(stg + (uint32_t)(A_STG + m * RSTRIDE + kc) * 4u,
                       W + (size_t)(nblk + m) * K + k0 + kc);
        }
    };

    auto compute = [&](int st) {
        const float* Ast = smem + st * STG_FLOATS;
        const float* Bst = Ast + A_STG;
#pragma unroll
        for (int k8 = 0; k8 < 2; k8++) {
            const int kb8 = k8 * 8;
            uint32_t af[2][4];
#pragma unroll
            for (int i = 0; i < 2; i++) {
                const int m0 = wm + i * 16;
                const float2 lo = *(const float2*)(Ast + (m0 + g    ) * RSTRIDE + kb8 + 2 * tg);
                const float2 hi = *(const float2*)(Ast + (m0 + g + 8) * RSTRIDE + kb8 + 2 * tg);
                af[i][0] = tf32bits(lo.x);
                af[i][1] = tf32bits(hi.x);
                af[i][2] = tf32bits(lo.y);
                af[i][3] = tf32bits(hi.y);
            }
            uint32_t bfr[8][2];
#pragma unroll
            for (int j = 0; j < 8; j++) {
                const int n0 = wn + j * 8;
                const float2 b2v = *(const float2*)(Bst + (n0 + g) * RSTRIDE + kb8 + 2 * tg);
                bfr[j][0] = tf32bits(b2v.x);
                bfr[j][1] = tf32bits(b2v.y);
            }
#pragma unroll
            for (int i = 0; i < 2; i++)
#pragma unroll
                for (int j = 0; j < 8; j++)
                    asm volatile(
                        "mma.sync.aligned.m16n8k8.row.col.f32.tf32.tf32.f32 "
                        "{%0,%1,%2,%3}, {%4,%5,%6,%7}, {%8,%9}, {%0,%1,%2,%3};\n"
                        : "+f"(acc[i][j][0]), "+f"(acc[i][j][1]),
                          "+f"(acc[i][j][2]), "+f"(acc[i][j][3])
                        : "r"(af[i][0]), "r"(af[i][1]), "r"(af[i][2]), "r"(af[i][3]),
                          "r"(bfr[j][0]), "r"(bfr[j][1]));
        }
    };

    const int KT = K / BK2;

    // prefetch NSTAGE-1 stages
#pragma unroll
    for (int p = 0; p < NSTAGE - 1; p++) {
        if (p < KT) issue(p, p);
        asm volatile("cp.async.commit_group;\n" ::);
    }

    // ONE barrier per iteration: the sync (after wait) orders previous iter's
    // compute before this iter's issue refills that stage.
    for (int kb = 0; kb < KT; kb++) {
        asm volatile("cp.async.wait_group %0;\n" :: "n"(NSTAGE - 2));
        __syncthreads();
        if (kb + NSTAGE - 1 < KT) issue((kb + NSTAGE - 1) % NSTAGE, kb + NSTAGE - 1);
        asm volatile("cp.async.commit_group;\n" ::);
        compute(kb % NSTAGE);
    }

    // epilogue
#pragma unroll
    for (int i = 0; i < 2; i++) {
        const int row_a = mblk + wm + i * 16 + g;
        const int row_b = row_a + 8;
#pragma unroll
        for (int j = 0; j < 8; j++) {
            const int col = nblk + wn + j * 8 + 2 * tg;
            const float2 bv = *(const float2*)(bias + col);
            float o0 = acc[i][j][0] + bv.x;
            float o1 = acc[i][j][1] + bv.y;
            float o2 = acc[i][j][2] + bv.x;
            float o3 = acc[i][j][3] + bv.y;
            if (RELU) {
                o0 = fmaxf(o0, 0.f); o1 = fmaxf(o1, 0.f);
                o2 = fmaxf(o2, 0.f); o3 = fmaxf(o3, 0.f);
            }
            if (MEAN) {
                // pair rows (2r, 2r+1) live in lanes g and g^1 (lane ^ 4)
                const float m0 = 0.5f * (o0 + __shfl_xor_sync(0xffffffffu, o0, 4));
                const float m1 = 0.5f * (o1 + __shfl_xor_sync(0xffffffffu, o1, 4));
                const float m2 = 0.5f * (o2 + __shfl_xor_sync(0xffffffffu, o2, 4));
                const float m3 = 0.5f * (o3 + __shfl_xor_sync(0xffffffffu, o3, 4));
                if ((g & 1) == 0) {
                    const size_t ra = (size_t)(row_a >> 1) * ldc + col;
                    const size_t rb = (size_t)(row_b >> 1) * ldc + col;
                    *(float2*)(C + ra) = make_float2(m0, m1);
                    *(float2*)(C + rb) = make_float2(m2, m3);
                }
            } else {
                const size_t ca = (size_t)(rowmul * row_a + rowadd) * ldc + col;
                const size_t cb = (size_t)(rowmul * row_b + rowadd) * ldc + col;
                *(float2*)(C + ca) = make_float2(o0, o1);
                *(float2*)(C + cb) = make_float2(o2, o3);
            }
        }
    }
}

// ---------------- LayerNorm (+opt relu), row length DIM ----------------
__global__ void ln_kernel(const float* __restrict__ in, float* __restrict__ out,
                          const float* __restrict__ g_e, const float* __restrict__ b_e,
                          const float* __restrict__ g_o, const float* __restrict__ b_o,
                          int relu)
{
    const int row = blockIdx.x;
    const int tid = threadIdx.x;
    const float* gg = (row & 1) ? g_o : g_e;
    const float* bb = (row & 1) ? b_o : b_e;

    float4 v = ((const float4*)(in + (size_t)row * DIM))[tid];
    float s = v.x + v.y + v.z + v.w;
    float q = v.x*v.x + v.y*v.y + v.z*v.z + v.w*v.w;
#pragma unroll
    for (int off = 16; off; off >>= 1) {
        s += __shfl_xor_sync(0xffffffffu, s, off);
        q += __shfl_xor_sync(0xffffffffu, q, off);
    }
    __shared__ float ss[8], sq[8];
    __shared__ float mu_s, rs_s;
    if ((tid & 31) == 0) { ss[tid >> 5] = s; sq[tid >> 5] = q; }
    __syncthreads();
    if (tid == 0) {
        float S = 0.f, Q = 0.f;
#pragma unroll
        for (int i = 0; i < 8; i++) { S += ss[i]; Q += sq[i]; }
        const float mu = S * (1.0f / DIM);
        const float var = Q * (1.0f / DIM) - mu * mu;
        mu_s = mu;
        rs_s = rsqrtf(var + 1e-5f);
    }
    __syncthreads();
    const float mu = mu_s, rs = rs_s;
    const float4 gv = ((const float4*)gg)[tid];
    const float4 bv = ((const float4*)bb)[tid];
    v.x = (v.x - mu) * rs * gv.x + bv.x;
    v.y = (v.y - mu) * rs * gv.y + bv.y;
    v.z = (v.z - mu) * rs * gv.z + bv.z;
    v.w = (v.w - mu) * rs * gv.w + bv.w;
    if (relu) {
        v.x = fmaxf(v.x, 0.f); v.y = fmaxf(v.y, 0.f);
        v.z = fmaxf(v.z, 0.f); v.w = fmaxf(v.w, 0.f);
    }
    ((float4*)(out + (size_t)row * DIM))[tid] = v;
}

__device__ __forceinline__ float lrelu(float v) { return v > 0.f ? v : 0.2f * v; }

// ---------------- GAT1 fixup rows 0,1 (H=2, in=1024, out/head=1024) ----------------
__global__ void fixup_gat1(const float* __restrict__ nodes, const float* __restrict__ W1,
                           const float* __restrict__ as1, const float* __restrict__ ad1,
                           const float* __restrict__ b1, float* __restrict__ x1)
{
    __shared__ float sh_n[2][DIM];
    __shared__ float sh_xp[2][2 * DIM];
    __shared__ float sh_sd[8];
    __shared__ float sh_w[8];
    const int tid = threadIdx.x, warp = tid >> 5, lane = tid & 31;

    for (int i = tid; i < 2 * DIM; i += 256) sh_n[i >> 10][i & 1023] = nodes[i];
    __syncthreads();

    for (int o = warp; o < 4096; o += 8) {
        const int n = o >> 11, oc = o & 2047;
        const float* wr = W1 + (size_t)oc * DIM;
        float p = 0.f;
        for (int k = lane; k < DIM; k += 32) p += sh_n[n][k] * wr[k];
#pragma unroll
        for (int off = 16; off; off >>= 1) p += __shfl_xor_sync(0xffffffffu, p, off);
        if (lane == 0) sh_xp[n][oc] = p;
    }
    __syncthreads();

    if (warp < 8) {
        const int n = warp >> 2, h = (warp >> 1) & 1, isd = warp & 1;
        const float* av = (isd ? ad1 : as1) + h * DIM;
        float p = 0.f;
        for (int k = lane; k < DIM; k += 32) p += sh_xp[n][h * DIM + k] * av[k];
#pragma unroll
        for (int off = 16; off; off >>= 1) p += __shfl_xor_sync(0xffffffffu, p, off);
        if (lane == 0) sh_sd[n * 4 + h * 2 + isd] = p;
    }
    __syncthreads();

    if (tid == 0) {
#pragma unroll
        for (int h = 0; h < 2; h++) {
            const float s0 = sh_sd[0*4 + h*2 + 0], d0 = sh_sd[0*4 + h*2 + 1];
            const float s1 = sh_sd[1*4 + h*2 + 0], d1 = sh_sd[1*4 + h*2 + 1];
            const float e00 = lrelu(s0 + d0), e10 = lrelu(s1 + d0);
            const float e11 = lrelu(s1 + d1), e01 = lrelu(s0 + d1);
            const float m0 = fmaxf(e00, e10);
            const float w00 = expf(e00 - m0), w10 = expf(e10 - m0);
            const float inv0 = 1.f / (w00 + w10);
            const float m1 = fmaxf(e11, e01);
            const float w11 = expf(e11 - m1), w01 = expf(e01 - m1);
            const float inv1 = 1.f / (w11 + w01);
            sh_w[h*4+0] = w00 * inv0;
            sh_w[h*4+1] = w10 * inv0;
            sh_w[h*4+2] = w11 * inv1;
            sh_w[h*4+3] = w01 * inv1;
        }
    }
    __syncthreads();

    for (int idx = tid; idx < 2 * DIM; idx += 256) {
        const int h = idx >> 10;
        const float o0 = sh_w[h*4+0] * sh_xp[0][idx] + sh_w[h*4+1] * sh_xp[1][idx];
        const float o1 = sh_w[h*4+2] * sh_xp[1][idx] + sh_w[h*4+3] * sh_xp[0][idx];
        x1[idx]           = fmaxf(o0 + b1[idx], 0.f);
        x1[2 * DIM + idx] = fmaxf(o1 + b1[idx], 0.f);
    }
}

// ---------------- GAT2 fixup rows 0,1 -> writes corrected xm row 0 ----------------
__global__ void fixup_gat2(const float* __restrict__ x1, const float* __restrict__ W2,
                           const float* __restrict__ as2, const float* __restrict__ ad2,
                           const float* __restrict__ b2, float* __restrict__ xm)
{
    __shared__ float sh_in[2][2 * DIM];
    __shared__ float sh_xp[2][DIM];
    __shared__ float sh_sd[4];
    __shared__ float sh_w[4];
    const int tid = threadIdx.x, warp = tid >> 5, lane = tid & 31;

    for (int i = tid; i < 4 * DIM; i += 256) sh_in[i >> 11][i & 2047] = x1[i];
    __syncthreads();

    for (int o = warp; o < 2048; o += 8) {
        const int n = o >> 10, oc = o & 1023;
        const float* wr = W2 + (size_t)oc * (2 * DIM);
        float p = 0.f;
        for (int k = lane; k < 2 * DIM; k += 32) p += sh_in[n][k] * wr[k];
#pragma unroll
        for (int off = 16; off; off >>= 1) p += __shfl_xor_sync(0xffffffffu, p, off);
        if (lane == 0) sh_xp[n][oc] = p;
    }
    __syncthreads();

    if (warp < 4) {
        const int n = warp >> 1, isd = warp & 1;
        const float* av = isd ? ad2 : as2;
        float p = 0.f;
        for (int k = lane; k < DIM; k += 32) p += sh_xp[n][k] * av[k];
#pragma unroll
        for (int off = 16; off; off >>= 1) p += __shfl_xor_sync(0xffffffffu, p, off);
        if (lane == 0) sh_sd[n * 2 + isd] = p;
    }
    __syncthreads();

    if (tid == 0) {
        const float s0 = sh_sd[0], d0 = sh_sd[1], s1 = sh_sd[2], d1 = sh_sd[3];
        const float e00 = lrelu(s0 + d0), e10 = lrelu(s1 + d0);
        const float e11 = lrelu(s1 + d1), e01 = lrelu(s0 + d1);
        const float m0 = fmaxf(e00, e10);
        const float w00 = expf(e00 - m0), w10 = expf(e10 - m0);
        const float inv0 = 1.f / (w00 + w10);
        const float m1 = fmaxf(e11, e01);
        const float w11 = expf(e11 - m1), w01 = expf(e01 - m1);
        const float inv1 = 1.f / (w11 + w01);
        sh_w[0] = w00 * inv0; sh_w[1] = w10 * inv0;
        sh_w[2] = w11 * inv1; sh_w[3] = w01 * inv1;
    }
    __syncthreads();

    for (int idx = tid; idx < DIM; idx += 256) {
        const float o0 = sh_w[0] * sh_xp[0][idx] + sh_w[1] * sh_xp[1][idx] + b2[idx];
        const float o1 = sh_w[2] * sh_xp[1][idx] + sh_w[3] * sh_xp[0][idx] + b2[idx];
        xm[idx] = 0.5f * (o0 + o1);   // corrected pair-mean for batch element 0
    }
}

// ---------------- launch ----------------
extern "C" void kernel_launch(void* const* d_in, const int* in_sizes, int n_in,
                              void* d_out, int out_size)
{
    const float* audio = (const float*)d_in[0];
    const float* text  = (const float*)d_in[1];
    const float* Wa    = (const float*)d_in[2];
    const float* ba    = (const float*)d_in[3];
    const float* lna_g = (const float*)d_in[4];
    const float* lna_b = (const float*)d_in[5];
    const float* Wt    = (const float*)d_in[6];
    const float* bt    = (const float*)d_in[7];
    const float* lnt_g = (const float*)d_in[8];
    const float* lnt_b = (const float*)d_in[9];
    const float* W1    = (const float*)d_in[10];
    const float* as1   = (const float*)d_in[11];
    const float* ad1   = (const float*)d_in[12];
    const float* b1    = (const float*)d_in[13];
    const float* W2    = (const float*)d_in[14];
    const float* as2   = (const float*)d_in[15];
    const float* ad2   = (const float*)d_in[16];
    const float* b2    = (const float*)d_in[17];
    const float* Wf    = (const float*)d_in[18];
    const float* bf    = (const float*)d_in[19];
    const float* lnf_g = (const float*)d_in[20];
    const float* lnf_b = (const float*)d_in[21];

    float *pre, *nodes, *x1, *xm, *fcb;
    cudaGetSymbolAddress((void**)&pre,   g_pre);
    cudaGetSymbolAddress((void**)&nodes, g_nodes);
    cudaGetSymbolAddress((void**)&x1,    g_x1);
    cudaGetSymbolAddress((void**)&xm,    g_xm);
    cudaGetSymbolAddress((void**)&fcb,   g_fcb);

    cudaFuncSetAttribute(gemm_big<0,0>, cudaFuncAttributeMaxDynamicSharedMemorySize, SMEM_BYTES);
    cudaFuncSetAttribute(gemm_big<1,0>, cudaFuncAttributeMaxDynamicSharedMemorySize, SMEM_BYTES);
    cudaFuncSetAttribute(gemm_big<0,1>, cudaFuncAttributeMaxDynamicSharedMemorySize, SMEM_BYTES);

    dim3 blk(NTHR);

    // proj_audio / proj_text -> interleaved pre-LN rows (row = 2*m + {0,1})
    gemm_big<0,0><<<dim3(8, 128), blk, SMEM_BYTES>>>(audio, Wa, ba, pre, 1024, 1024, 2, 0);
    gemm_big<0,0><<<dim3(8, 128), blk, SMEM_BYTES>>>(text,  Wt, bt, pre, 1024, 1024, 2, 1);
    // LN + relu (gain/bias by row parity)
    ln_kernel<<<NNODES, 256>>>(pre, nodes, lna_g, lna_b, lnt_g, lnt_b, 1);
    // gat1 self-loop path: relu(xp + b1)
    gemm_big<1,0><<<dim3(16, 256), blk, SMEM_BYTES>>>(nodes, W1, b1, x1, 1024, 2048, 1, 0);
    fixup_gat1<<<1, 256>>>(nodes, W1, as1, ad1, b1, x1);
    // gat2 self-loop path + FUSED pair-mean -> xm
    gemm_big<0,1><<<dim3(8, 256), blk, SMEM_BYTES>>>(x1, W2, b2, xm, 2048, 1024, 1, 0);
    fixup_gat2<<<1, 256>>>(x1, W2, as2, ad2, b2, xm);
    // fc on xm
    gemm_big<0,0><<<dim3(8, 128), blk, SMEM_BYTES>>>(xm, Wf, bf, fcb, 1024, 1024, 1, 0);
    // final LN -> out
    ln_kernel<<<BATCH, 256>>>(fcb, (float*)d_out, lnf_g, lnf_b, lnf_g, lnf_b, 0);
}

// round 12
// speedup vs baseline: 1.3278x; 1.1954x over previous
#include <cuda_runtime.h>
#include <cstdint>
#include <cstddef>
#include <math.h>

#define BATCH 16384
#define DIM   1024
#define NNODES (2*BATCH)

// ---------------- scratch (static device memory: allowed) ----------------
__device__ float g_pre    [(size_t)NNODES * DIM];      // proj out pre-LN (interleaved)
__device__ float g_nodes  [(size_t)NNODES * DIM];      // post LN+relu
__device__ float g_xmean1 [(size_t)BATCH * 2 * DIM];   // pair-mean of gat1 out (fused)
__device__ float g_x1row01[2 * 2 * DIM];               // exact x1 rows 0,1 (attention)
__device__ float g_xm     [(size_t)BATCH * DIM];       // gat2 out on xmean1 (= pair-mean of x2)
__device__ float g_fcb    [(size_t)BATCH * DIM];       // fc out pre-LN

__device__ __forceinline__ uint32_t tf32bits(float x) {
    uint32_t y;
    asm("cvt.rna.tf32.f32 %0, %1;" : "=r"(y) : "f"(x));
    return y;
}

__device__ __forceinline__ void cp_async16(uint32_t smem_dst, const void* gsrc) {
    asm volatile("cp.async.cg.shared.global [%0], [%1], 16;\n"
                 :: "r"(smem_dst), "l"(gsrc));
}

// ---------------- tf32 GEMM: C = A @ W^T (+bias, opt relu, opt pair-mean) ----------
// Block tile 128(M) x 128(N) x 16(K); 8 warps of 32x64; 4-stage cp.async ring;
// 2 CTAs per SM. cvt.rna.tf32 post-LDS. K within each k8 permuted (pos j <-> k=2j /
// 2j-7): float2 LDS, lo.x->pos tg, lo.y->pos tg+4 (K-sum order-invariant).
// MEAN=1: C row r gets 0.5*(out[2r]+out[2r+1]) via shfl across lane^4 (after RELU).
#define BM2 128
#define BN2 128
#define BK2 16
#define NTHR 256
#define RSTRIDE 24                        // floats per smem row (96B, 16B aligned)
#define A_STG (BM2 * RSTRIDE)             // 3072 floats
#define B_STG (BM2 * RSTRIDE)             // 3072 floats
#define STG_FLOATS (A_STG + B_STG)        // 6144 floats = 24576 B
#define NSTAGE 4
#define SMEM_BYTES (NSTAGE * STG_FLOATS * 4)   // 98304 B

template<int RELU, int MEAN>
__launch_bounds__(NTHR, 2)
__global__ void gemm_big(const float* __restrict__ A, const float* __restrict__ W,
                         const float* __restrict__ bias, float* __restrict__ C,
                         int K, int ldc, int rowmul, int rowadd)
{
    extern __shared__ float smem[];

    const int tid  = threadIdx.x;
    const int warp = tid >> 5;           // 0..7
    const int lane = tid & 31;
    const int g    = lane >> 2;          // 0..7
    const int tg   = lane & 3;           // 0..3
    const int wm   = (warp & 3) * 32;    // 0/32/64/96
    const int wn   = (warp >> 2) * 64;   // 0/64
    const int mblk = blockIdx.y * BM2;
    const int nblk = blockIdx.x * BN2;

    uint32_t smem_base;
    {
        void* p = smem;
        smem_base = (uint32_t)__cvta_generic_to_shared(p);
    }

    float acc[2][8][4];
#pragma unroll
    for (int i = 0; i < 2; i++)
#pragma unroll
        for (int j = 0; j < 8; j++)
#pragma unroll
            for (int q = 0; q < 4; q++) acc[i][j][q] = 0.f;

    auto issue = [&](int st, int kb) {
        const int k0 = kb * BK2;
        const uint32_t stg = smem_base + (uint32_t)(st * STG_FLOATS) * 4u;
#pragma unroll
        for (int i = 0; i < 2; i++) {
            const int c  = tid + i * NTHR;      // 0..511
            const int m  = c >> 2;              // 0..127
            const int kc = (c & 3) * 4;
            cp_async16(stg + (uint32_t)(m * RSTRIDE + kc) * 4u,
                       A + (size_t)(mblk + m) * K + k0 + kc);
            cp_async16(stg + (uint32_t)(A_STG + m * RSTRIDE + kc) * 4u,
                       W + (size_t)(nblk + m) * K + k0 + kc);
        }
    };

    auto compute = [&](int st) {
        const float* Ast = smem + st * STG_FLOATS;
        const float* Bst = Ast + A_STG;
#pragma unroll
        for (int k8 = 0; k8 < 2; k8++) {
            const int kb8 = k8 * 8;
            uint32_t af[2][4];
#pragma unroll
            for (int i = 0; i < 2; i++) {
                const int m0 = wm + i * 16;
                const float2 lo = *(const float2*)(Ast + (m0 + g    ) * RSTRIDE + kb8 + 2 * tg);
                const float2 hi = *(const float2*)(Ast + (m0 + g + 8) * RSTRIDE + kb8 + 2 * tg);
                af[i][0] = tf32bits(lo.x);
                af[i][1] = tf32bits(hi.x);
                af[i][2] = tf32bits(lo.y);
                af[i][3] = tf32bits(hi.y);
            }
            uint32_t bfr[8][2];
#pragma unroll
            for (int j = 0; j < 8; j++) {
                const int n0 = wn + j * 8;
                const float2 b2v = *(const float2*)(Bst + (n0 + g) * RSTRIDE + kb8 + 2 * tg);
                bfr[j][0] = tf32bits(b2v.x);
                bfr[j][1] = tf32bits(b2v.y);
            }
#pragma unroll
            for (int i = 0; i < 2; i++)
#pragma unroll
                for (int j = 0; j < 8; j++)
                    asm volatile(
                        "mma.sync.aligned.m16n8k8.row.col.f32.tf32.tf32.f32 "
                        "{%0,%1,%2,%3}, {%4,%5,%6,%7}, {%8,%9}, {%0,%1,%2,%3};\n"
                        : "+f"(acc[i][j][0]), "+f"(acc[i][j][1]),
                          "+f"(acc[i][j][2]), "+f"(acc[i][j][3])
                        : "r"(af[i][0]), "r"(af[i][1]), "r"(af[i][2]), "r"(af[i][3]),
                          "r"(bfr[j][0]), "r"(bfr[j][1]));
        }
    };

    const int KT = K / BK2;

#pragma unroll
    for (int p = 0; p < NSTAGE - 1; p++) {
        if (p < KT) issue(p, p);
        asm volatile("cp.async.commit_group;\n" ::);
    }

    for (int kb = 0; kb < KT; kb++) {
        asm volatile("cp.async.wait_group %0;\n" :: "n"(NSTAGE - 2));
        __syncthreads();
        if (kb + NSTAGE - 1 < KT) issue((kb + NSTAGE - 1) % NSTAGE, kb + NSTAGE - 1);
        asm volatile("cp.async.commit_group;\n" ::);
        compute(kb % NSTAGE);
        __syncthreads();
    }

    // epilogue
#pragma unroll
    for (int i = 0; i < 2; i++) {
        const int row_a = mblk + wm + i * 16 + g;
        const int row_b = row_a + 8;
#pragma unroll
        for (int j = 0; j < 8; j++) {
            const int col = nblk + wn + j * 8 + 2 * tg;
            const float2 bv = *(const float2*)(bias + col);
            float o0 = acc[i][j][0] + bv.x;
            float o1 = acc[i][j][1] + bv.y;
            float o2 = acc[i][j][2] + bv.x;
            float o3 = acc[i][j][3] + bv.y;
            if (RELU) {
                o0 = fmaxf(o0, 0.f); o1 = fmaxf(o1, 0.f);
                o2 = fmaxf(o2, 0.f); o3 = fmaxf(o3, 0.f);
            }
            if (MEAN) {
                // pair rows (2r, 2r+1) sit in lanes g and g^1 (lane ^ 4)
                const float m0 = 0.5f * (o0 + __shfl_xor_sync(0xffffffffu, o0, 4));
                const float m1 = 0.5f * (o1 + __shfl_xor_sync(0xffffffffu, o1, 4));
                const float m2 = 0.5f * (o2 + __shfl_xor_sync(0xffffffffu, o2, 4));
                const float m3 = 0.5f * (o3 + __shfl_xor_sync(0xffffffffu, o3, 4));
                if ((g & 1) == 0) {
                    const size_t ra = (size_t)(row_a >> 1) * ldc + col;
                    const size_t rb = (size_t)(row_b >> 1) * ldc + col;
                    *(float2*)(C + ra) = make_float2(m0, m1);
                    *(float2*)(C + rb) = make_float2(m2, m3);
                }
            } else {
                const size_t ca = (size_t)(rowmul * row_a + rowadd) * ldc + col;
                const size_t cb = (size_t)(rowmul * row_b + rowadd) * ldc + col;
                *(float2*)(C + ca) = make_float2(o0, o1);
                *(float2*)(C + cb) = make_float2(o2, o3);
            }
        }
    }
}

// ---------------- LayerNorm (+opt relu), row length DIM ----------------
__global__ void ln_kernel(const float* __restrict__ in, float* __restrict__ out,
                          const float* __restrict__ g_e, const float* __restrict__ b_e,
                          const float* __restrict__ g_o, const float* __restrict__ b_o,
                          int relu)
{
    const int row = blockIdx.x;
    const int tid = threadIdx.x;
    const float* gg = (row & 1) ? g_o : g_e;
    const float* bb = (row & 1) ? b_o : b_e;

    float4 v = ((const float4*)(in + (size_t)row * DIM))[tid];
    float s = v.x + v.y + v.z + v.w;
    float q = v.x*v.x + v.y*v.y + v.z*v.z + v.w*v.w;
#pragma unroll
    for (int off = 16; off; off >>= 1) {
        s += __shfl_xor_sync(0xffffffffu, s, off);
        q += __shfl_xor_sync(0xffffffffu, q, off);
    }
    __shared__ float ss[8], sq[8];
    __shared__ float mu_s, rs_s;
    if ((tid & 31) == 0) { ss[tid >> 5] = s; sq[tid >> 5] = q; }
    __syncthreads();
    if (tid == 0) {
        float S = 0.f, Q = 0.f;
#pragma unroll
        for (int i = 0; i < 8; i++) { S += ss[i]; Q += sq[i]; }
        const float mu = S * (1.0f / DIM);
        const float var = Q * (1.0f / DIM) - mu * mu;
        mu_s = mu;
        rs_s = rsqrtf(var + 1e-5f);
    }
    __syncthreads();
    const float mu = mu_s, rs = rs_s;
    const float4 gv = ((const float4*)gg)[tid];
    const float4 bv = ((const float4*)bb)[tid];
    v.x = (v.x - mu) * rs * gv.x + bv.x;
    v.y = (v.y - mu) * rs * gv.y + bv.y;
    v.z = (v.z - mu) * rs * gv.z + bv.z;
    v.w = (v.w - mu) * rs * gv.w + bv.w;
    if (relu) {
        v.x = fmaxf(v.x, 0.f); v.y = fmaxf(v.y, 0.f);
        v.z = fmaxf(v.z, 0.f); v.w = fmaxf(v.w, 0.f);
    }
    ((float4*)(out + (size_t)row * DIM))[tid] = v;
}

__device__ __forceinline__ float lrelu(float v) { return v > 0.f ? v : 0.2f * v; }

// ---------------- GAT1 fixup rows 0,1: writes x1row01 + patches xmean1[0] --------
__global__ void fixup_gat1(const float* __restrict__ nodes, const float* __restrict__ W1,
                           const float* __restrict__ as1, const float* __restrict__ ad1,
                           const float* __restrict__ b1, float* __restrict__ x1row01,
                           float* __restrict__ xmean1)
{
    __shared__ float sh_n[2][DIM];
    __shared__ float sh_xp[2][2 * DIM];
    __shared__ float sh_sd[8];
    __shared__ float sh_w[8];
    const int tid = threadIdx.x, warp = tid >> 5, lane = tid & 31;

    for (int i = tid; i < 2 * DIM; i += 256) sh_n[i >> 10][i & 1023] = nodes[i];
    __syncthreads();

    for (int o = warp; o < 4096; o += 8) {
        const int n = o >> 11, oc = o & 2047;
        const float* wr = W1 + (size_t)oc * DIM;
        float p = 0.f;
        for (int k = lane; k < DIM; k += 32) p += sh_n[n][k] * wr[k];
#pragma unroll
        for (int off = 16; off; off >>= 1) p += __shfl_xor_sync(0xffffffffu, p, off);
        if (lane == 0) sh_xp[n][oc] = p;
    }
    __syncthreads();

    if (warp < 8) {
        const int n = warp >> 2, h = (warp >> 1) & 1, isd = warp & 1;
        const float* av = (isd ? ad1 : as1) + h * DIM;
        float p = 0.f;
        for (int k = lane; k < DIM; k += 32) p += sh_xp[n][h * DIM + k] * av[k];
#pragma unroll
        for (int off = 16; off; off >>= 1) p += __shfl_xor_sync(0xffffffffu, p, off);
        if (lane == 0) sh_sd[n * 4 + h * 2 + isd] = p;
    }
    __syncthreads();

    if (tid == 0) {
#pragma unroll
        for (int h = 0; h < 2; h++) {
            const float s0 = sh_sd[0*4 + h*2 + 0], d0 = sh_sd[0*4 + h*2 + 1];
            const float s1 = sh_sd[1*4 + h*2 + 0], d1 = sh_sd[1*4 + h*2 + 1];
            const float e00 = lrelu(s0 + d0), e10 = lrelu(s1 + d0);
            const float e11 = lrelu(s1 + d1), e01 = lrelu(s0 + d1);
            const float m0 = fmaxf(e00, e10);
            const float w00 = expf(e00 - m0), w10 = expf(e10 - m0);
            const float inv0 = 1.f / (w00 + w10);
            const float m1 = fmaxf(e11, e01);
            const float w11 = expf(e11 - m1), w01 = expf(e01 - m1);
            const float inv1 = 1.f / (w11 + w01);
            sh_w[h*4+0] = w00 * inv0;
            sh_w[h*4+1] = w10 * inv0;
            sh_w[h*4+2] = w11 * inv1;
            sh_w[h*4+3] = w01 * inv1;
        }
    }
    __syncthreads();

    for (int idx = tid; idx < 2 * DIM; idx += 256) {
        const int h = idx >> 10;
        const float o0 = sh_w[h*4+0] * sh_xp[0][idx] + sh_w[h*4+1] * sh_xp[1][idx];
        const float o1 = sh_w[h*4+2] * sh_xp[1][idx] + sh_w[h*4+3] * sh_xp[0][idx];
        const float r0 = fmaxf(o0 + b1[idx], 0.f);
        const float r1 = fmaxf(o1 + b1[idx], 0.f);
        x1row01[idx]           = r0;
        x1row01[2 * DIM + idx] = r1;
        xmean1[idx] = 0.5f * (r0 + r1);   // corrected pair-mean row 0
    }
}

// ---------------- GAT2 fixup: recompute xm[0] exactly from x1 rows 0,1 ----------
__global__ void fixup_gat2(const float* __restrict__ x1row01, const float* __restrict__ W2,
                           const float* __restrict__ as2, const float* __restrict__ ad2,
                           const float* __restrict__ b2, float* __restrict__ xm)
{
    __shared__ float sh_in[2][2 * DIM];
    __shared__ float sh_xp[2][DIM];
    __shared__ float sh_sd[4];
    __shared__ float sh_w[4];
    const int tid = threadIdx.x, warp = tid >> 5, lane = tid & 31;

    for (int i = tid; i < 4 * DIM; i += 256) sh_in[i >> 11][i & 2047] = x1row01[i];
    __syncthreads();

    for (int o = warp; o < 2048; o += 8) {
        const int n = o >> 10, oc = o & 1023;
        const float* wr = W2 + (size_t)oc * (2 * DIM);
        float p = 0.f;
        for (int k = lane; k < 2 * DIM; k += 32) p += sh_in[n][k] * wr[k];
#pragma unroll
        for (int off = 16; off; off >>= 1) p += __shfl_xor_sync(0xffffffffu, p, off);
        if (lane == 0) sh_xp[n][oc] = p;
    }
    __syncthreads();

    if (warp < 4) {
        const int n = warp >> 1, isd = warp & 1;
        const float* av = isd ? ad2 : as2;
        float p = 0.f;
        for (int k = lane; k < DIM; k += 32) p += sh_xp[n][k] * av[k];
#pragma unroll
        for (int off = 16; off; off >>= 1) p += __shfl_xor_sync(0xffffffffu, p, off);
        if (lane == 0) sh_sd[n * 2 + isd] = p;
    }
    __syncthreads();

    if (tid == 0) {
        const float s0 = sh_sd[0], d0 = sh_sd[1], s1 = sh_sd[2], d1 = sh_sd[3];
        const float e00 = lrelu(s0 + d0), e10 = lrelu(s1 + d0);
        const float e11 = lrelu(s1 + d1), e01 = lrelu(s0 + d1);
        const float m0 = fmaxf(e00, e10);
        const float w00 = expf(e00 - m0), w10 = expf(e10 - m0);
        const float inv0 = 1.f / (w00 + w10);
        const float m1 = fmaxf(e11, e01);
        const float w11 = expf(e11 - m1), w01 = expf(e01 - m1);
        const float inv1 = 1.f / (w11 + w01);
        sh_w[0] = w00 * inv0; sh_w[1] = w10 * inv0;
        sh_w[2] = w11 * inv1; sh_w[3] = w01 * inv1;
    }
    __syncthreads();

    for (int idx = tid; idx < DIM; idx += 256) {
        const float o0 = sh_w[0] * sh_xp[0][idx] + sh_w[1] * sh_xp[1][idx] + b2[idx];
        const float o1 = sh_w[2] * sh_xp[1][idx] + sh_w[3] * sh_xp[0][idx] + b2[idx];
        xm[idx] = 0.5f * (o0 + o1);   // exact pair-mean for batch element 0
    }
}

// ---------------- launch ----------------
extern "C" void kernel_launch(void* const* d_in, const int* in_sizes, int n_in,
                              void* d_out, int out_size)
{
    const float* audio = (const float*)d_in[0];
    const float* text  = (const float*)d_in[1];
    const float* Wa    = (const float*)d_in[2];
    const float* ba    = (const float*)d_in[3];
    const float* lna_g = (const float*)d_in[4];
    const float* lna_b = (const float*)d_in[5];
    const float* Wt    = (const float*)d_in[6];
    const float* bt    = (const float*)d_in[7];
    const float* lnt_g = (const float*)d_in[8];
    const float* lnt_b = (const float*)d_in[9];
    const float* W1    = (const float*)d_in[10];
    const float* as1   = (const float*)d_in[11];
    const float* ad1   = (const float*)d_in[12];
    const float* b1    = (const float*)d_in[13];
    const float* W2    = (const float*)d_in[14];
    const float* as2   = (const float*)d_in[15];
    const float* ad2   = (const float*)d_in[16];
    const float* b2    = (const float*)d_in[17];
    const float* Wf    = (const float*)d_in[18];
    const float* bf    = (const float*)d_in[19];
    const float* lnf_g = (const float*)d_in[20];
    const float* lnf_b = (const float*)d_in[21];

    float *pre, *nodes, *xmean1, *x1row01, *xm, *fcb;
    cudaGetSymbolAddress((void**)&pre,     g_pre);
    cudaGetSymbolAddress((void**)&nodes,   g_nodes);
    cudaGetSymbolAddress((void**)&xmean1,  g_xmean1);
    cudaGetSymbolAddress((void**)&x1row01, g_x1row01);
    cudaGetSymbolAddress((void**)&xm,      g_xm);
    cudaGetSymbolAddress((void**)&fcb,     g_fcb);

    cudaFuncSetAttribute(gemm_big<0,0>, cudaFuncAttributeMaxDynamicSharedMemorySize, SMEM_BYTES);
    cudaFuncSetAttribute(gemm_big<1,1>, cudaFuncAttributeMaxDynamicSharedMemorySize, SMEM_BYTES);

    dim3 blk(NTHR);

    // proj_audio / proj_text -> interleaved pre-LN rows (row = 2*m + {0,1})
    gemm_big<0,0><<<dim3(8, 128), blk, SMEM_BYTES>>>(audio, Wa, ba, pre, 1024, 1024, 2, 0);
    gemm_big<0,0><<<dim3(8, 128), blk, SMEM_BYTES>>>(text,  Wt, bt, pre, 1024, 1024, 2, 1);
    // LN + relu (gain/bias by row parity)
    ln_kernel<<<NNODES, 256>>>(pre, nodes, lna_g, lna_b, lnt_g, lnt_b, 1);
    // gat1 self-loop path + relu + FUSED pair-mean -> xmean1 [BATCH, 2*DIM]
    gemm_big<1,1><<<dim3(16, 256), blk, SMEM_BYTES>>>(nodes, W1, b1, xmean1, 1024, 2048, 1, 0);
    // exact attention x1 rows 0,1 + patch xmean1 row 0 (must precede gat2 GEMM)
    fixup_gat1<<<1, 256>>>(nodes, W1, as1, ad1, b1, x1row01, xmean1);
    // gat2 on pre-meaned input (affine => mean commutes): xm = xmean1 @ W2^T + b2
    gemm_big<0,0><<<dim3(8, 128), blk, SMEM_BYTES>>>(xmean1, W2, b2, xm, 2048, 1024, 1, 0);
    // exact xm[0] from attention-mixed gat2 on x1 rows 0,1 (after gat2 GEMM)
    fixup_gat2<<<1, 256>>>(x1row01, W2, as2, ad2, b2, xm);
    // fc on xm
    gemm_big<0,0><<<dim3(8, 128), blk, SMEM_BYTES>>>(xm, Wf, bf, fcb, 1024, 1024, 1, 0);
    // final LN -> out
    ln_kernel<<<BATCH, 256>>>(fcb, (float*)d_out, lnf_g, lnf_b, lnf_g, lnf_b, 0);
}